// round 5
// baseline (speedup 1.0000x reference)
#include <cuda_runtime.h>
#include <math_constants.h>

#define BATCH     16
#define FRAMES    4000
#define BINS      257
#define HOP       128
#define G         25
#define NGROUPS   160
#define FRAMES_SH 28
#define NPAIRS    14
#define OUT_LEN   512383
#define SWZ4(i)   ((i) ^ (((i) >> 3) & 7))

typedef unsigned long long u64;
#define NEG1P 0xBF800000BF800000ULL

// dynamic smem layout (bytes)
#define OFF_FR    0                         // 28*512*4 = 57344
#define OFF_WIN   57344                     // 512 floats = 2048 (natural order)
#define OFF_PC    59392                     // 256 u64 = 2048
#define OFF_NPS   61440
#define OFF_NPC   63488
#define OFF_LTW   65536                     // 37*32 u64 = 9472
#define SMEM_BYTES 75008

__device__ __forceinline__ u64 pk2(float a, float b) {
    u64 r; asm("mov.b64 %0, {%1,%2};" : "=l"(r) : "f"(a), "f"(b)); return r;
}
__device__ __forceinline__ float2 up2(u64 v) {
    float2 f; asm("mov.b64 {%0,%1}, %2;" : "=f"(f.x), "=f"(f.y) : "l"(v)); return f;
}
__device__ __forceinline__ u64 add2(u64 a, u64 b) {
    u64 r; asm("add.rn.f32x2 %0,%1,%2;" : "=l"(r) : "l"(a), "l"(b)); return r;
}
__device__ __forceinline__ u64 mul2(u64 a, u64 b) {
    u64 r; asm("mul.rn.f32x2 %0,%1,%2;" : "=l"(r) : "l"(a), "l"(b)); return r;
}
__device__ __forceinline__ u64 fma2_(u64 a, u64 b, u64 c) {
    u64 r; asm("fma.rn.f32x2 %0,%1,%2,%3;" : "=l"(r) : "l"(a), "l"(b), "l"(c)); return r;
}
__device__ __forceinline__ u64 shfl2x(u64 v, int m) {
    float2 f = up2(v);
    f.x = __shfl_xor_sync(0xffffffffu, f.x, m);
    f.y = __shfl_xor_sync(0xffffffffu, f.y, m);
    return pk2(f.x, f.y);
}

__global__ __launch_bounds__(256, 2)
void istft_kernel(const float* __restrict__ xr,
                  const float* __restrict__ xi,
                  float* __restrict__ out)
{
    extern __shared__ __align__(16) char smem_raw[];
    float* fr   = (float*)(smem_raw + OFF_FR);
    float* ww   = (float*)(smem_raw + OFF_WIN);
    u64*  pcA   = (u64*)(smem_raw + OFF_PC);
    u64*  npsA  = (u64*)(smem_raw + OFF_NPS);
    u64*  npcA  = (u64*)(smem_raw + OFF_NPC);
    u64*  ltw   = (u64*)(smem_raw + OFF_LTW);

    const int tid   = threadIdx.x;     // 256
    const int warp  = tid >> 5;
    const int lane  = tid & 31;
    const int group = blockIdx.x;
    const int batch = blockIdx.y;
    const int f0     = group * G;
    const int fstart = f0 - 3;

    // window: hann(n)/(1.5*512), natural order (applied at gather)
    for (int n = tid; n < 512; n += 256) {
        ww[n] = (0.5f - 0.5f * cosf(2.0f * CUDART_PI_F * (float)n * (1.0f / 512.0f)))
                * (1.0f / 768.0f);
    }
    // prerot tables: e^{i*pi*k/256} as (c), (-s), (-c), duplicated-packed
    {
        int k = tid;
        float s, c;
        sincosf(CUDART_PI_F * (float)k * (1.0f / 256.0f), &s, &c);
        pcA[k]  = pk2(c, c);
        npsA[k] = pk2(-s, -s);
        npcA[k] = pk2(-c, -c);
    }
    // per-lane twiddle table (SoA: item i at ltw[i*32+lane])
    if (tid < 32) {
        const float R2 = 0.70710678118654752f;
        float s128, c128; sincosf(CUDART_PI_F * (float)lane * (1.0f / 128.0f), &s128, &c128);
        float s64,  c64;  sincosf(CUDART_PI_F * (float)lane * (1.0f / 64.0f),  &s64,  &c64);
        float s32,  c32;  sincosf(CUDART_PI_F * (float)lane * (1.0f / 32.0f),  &s32,  &c32);
        #define PUT(i, v) ltw[(i) * 32 + lane] = pk2((v), (v))
        // h128 twiddles: e^{i*pi*lane/128} * e^{i*pi*j/4}, stored (C, S, -S)
        PUT(0,  c128);                 PUT(1,  s128);                 PUT(2,  -s128);
        PUT(3,  R2 * (c128 - s128));   PUT(4,  R2 * (c128 + s128));   PUT(5,  -R2 * (c128 + s128));
        PUT(6,  -s128);                PUT(7,  c128);                 PUT(8,  -c128);
        PUT(9,  -R2 * (c128 + s128));  PUT(10, R2 * (c128 - s128));   PUT(11, -R2 * (c128 - s128));
        // h64: typeA = t64, typeB = i*t64
        PUT(12, c64);  PUT(13, s64);  PUT(14, -s64);
        PUT(15, -s64); PUT(16, c64);  PUT(17, -c64);
        // h32
        PUT(18, c32);  PUT(19, s32);  PUT(20, -s32);
        // lane stages m=16,8,4: (S, Wc, Ws, -Ws)
        {
            float s16, c16; sincosf(CUDART_PI_F * (float)(lane & 15) * (1.0f / 16.0f), &s16, &c16);
            bool hi = (lane & 16) != 0;
            PUT(21, hi ? -1.f : 1.f); PUT(22, hi ? c16 : 1.f);
            PUT(23, hi ? s16 : 0.f);  PUT(24, hi ? -s16 : 0.f);
        }
        {
            float s8, c8; sincosf(CUDART_PI_F * (float)(lane & 7) * (1.0f / 8.0f), &s8, &c8);
            bool hi = (lane & 8) != 0;
            PUT(25, hi ? -1.f : 1.f); PUT(26, hi ? c8 : 1.f);
            PUT(27, hi ? s8 : 0.f);   PUT(28, hi ? -s8 : 0.f);
        }
        {
            float s4, c4; sincosf(CUDART_PI_F * (float)(lane & 3) * (1.0f / 4.0f), &s4, &c4);
            bool hi = (lane & 4) != 0;
            PUT(29, hi ? -1.f : 1.f); PUT(30, hi ? c4 : 1.f);
            PUT(31, hi ? s4 : 0.f);   PUT(32, hi ? -s4 : 0.f);
        }
        {   // m=2: W = (rot ? i : 1) when hi
            bool hi  = (lane & 2) != 0;
            bool rot = (lane & 1) != 0;
            PUT(33, hi ? -1.f : 1.f);
            PUT(34, hi ? (rot ? 0.f : 1.f) : 1.f);
            PUT(35, hi ? (rot ? 1.f : 0.f) : 0.f);
            PUT(36, hi ? (rot ? -1.f : 0.f) : 0.f);
        }
        #undef PUT
    }
    if (group == 0)
        for (int i = tid; i < 3 * 512; i += 256) fr[i] = 0.f;
    __syncthreads();

    const u64 S1   = pk2((lane & 1) ? -1.f : 1.f, (lane & 1) ? -1.f : 1.f);
    const int rl   = (int)(__brev((unsigned)lane) >> 27);   // rev5(lane)
    const u64* ltwL = ltw + lane;
    const size_t bbase = (size_t)batch * FRAMES;

    // ---- frame pairs: each warp computes 2 frames at once (packed f32x2) ----
    for (int p = warp; p < NPAIRS; p += 8) {
        const int lfA = 2 * p, lfB = 2 * p + 1;
        const int fA = fstart + lfA, fB = fA + 1;
        const bool vA = (fA >= 0), vB = (fB >= 0);
        const int fAc = vA ? fA : 0, fBc = vB ? fB : 0;

        const float* prA = xr + (bbase + fAc) * BINS;
        const float* prB = xr + (bbase + fBc) * BINS;
        const float* piA = xi + (bbase + fAc) * BINS;
        const float* piB = xi + (bbase + fBc) * BINS;

        u64 zr[8], zi[8];

        // Hermitian pack + pre-rotation, k = 32*j + lane (coalesced loads)
        #pragma unroll
        for (int j = 0; j < 8; j++) {
            const int k = 32 * j + lane, km = 256 - k;
            float arA = prA[k],  arB = prB[k];
            float brA = prA[km], brB = prB[km];
            float aiA, aiB, miA, miB;
            if (k == 0) { aiA = aiB = miA = miB = 0.f; }
            else { aiA = piA[k]; aiB = piB[k]; miA = piA[km]; miB = piB[km]; }
            u64 ar = pk2(arA, arB), br = pk2(brA, brB);
            u64 ai = pk2(aiA, aiB), mi = pk2(miA, miB);
            u64 er = add2(ar, br);
            u64 dr = fma2_(br, NEG1P, ar);
            u64 ei = fma2_(mi, NEG1P, ai);      // ai - mi  (bi = -mi)
            u64 di = add2(ai, mi);
            u64 pc = pcA[k], nps = npsA[k], npc = npcA[k];
            zr[j] = fma2_(di, npc, fma2_(dr, nps, er));   // er - dr*s - di*c
            zi[j] = fma2_(di, nps, fma2_(dr, pc,  ei));   // ei + dr*c - di*s
        }

        #define BFLY(A, B, C, S, NS) {                                  \
            u64 ur = add2(zr[A], zr[B]);                                 \
            u64 ui = add2(zi[A], zi[B]);                                 \
            u64 tr = fma2_(zr[B], NEG1P, zr[A]);                         \
            u64 ti = fma2_(zi[B], NEG1P, zi[A]);                         \
            zr[A] = ur; zi[A] = ui;                                      \
            zr[B] = fma2_(ti, (NS), mul2(tr, (C)));                      \
            zi[B] = fma2_(ti, (C),  mul2(tr, (S)));                      \
        }
        // stage h=128: pairs (j, j+4)
        #pragma unroll
        for (int j = 0; j < 4; j++) {
            u64 C = ltwL[(3 * j + 0) * 32], S = ltwL[(3 * j + 1) * 32], NS = ltwL[(3 * j + 2) * 32];
            BFLY(j, j + 4, C, S, NS);
        }
        // stage h=64
        {
            u64 Ca = ltwL[12 * 32], Sa = ltwL[13 * 32], Na = ltwL[14 * 32];
            u64 Cb = ltwL[15 * 32], Sb = ltwL[16 * 32], Nb = ltwL[17 * 32];
            BFLY(0, 2, Ca, Sa, Na) BFLY(4, 6, Ca, Sa, Na)
            BFLY(1, 3, Cb, Sb, Nb) BFLY(5, 7, Cb, Sb, Nb)
        }
        // stage h=32
        {
            u64 C = ltwL[18 * 32], S = ltwL[19 * 32], N = ltwL[20 * 32];
            BFLY(0, 1, C, S, N) BFLY(2, 3, C, S, N)
            BFLY(4, 5, C, S, N) BFLY(6, 7, C, S, N)
        }
        #undef BFLY

        // lane stages m = 16, 8, 4, 2 (unified, branch-free)
        const int masks[4] = {16, 8, 4, 2};
        #pragma unroll
        for (int st = 0; st < 4; st++) {
            const int ib = 21 + 4 * st;
            u64 Sg  = ltwL[(ib + 0) * 32];
            u64 Wc  = ltwL[(ib + 1) * 32];
            u64 Ws  = ltwL[(ib + 2) * 32];
            u64 nWs = ltwL[(ib + 3) * 32];
            const int mk = masks[st];
            #pragma unroll
            for (int j = 0; j < 8; j++) {
                u64 orr = shfl2x(zr[j], mk);
                u64 oii = shfl2x(zi[j], mk);
                u64 tr = fma2_(zr[j], Sg, orr);
                u64 ti = fma2_(zi[j], Sg, oii);
                zr[j] = fma2_(ti, nWs, mul2(tr, Wc));
                zi[j] = fma2_(ti, Wc,  mul2(tr, Ws));
            }
        }
        // lane stage m = 1 (W = 1)
        #pragma unroll
        for (int j = 0; j < 8; j++) {
            u64 orr = shfl2x(zr[j], 1);
            u64 oii = shfl2x(zi[j], 1);
            zr[j] = fma2_(zr[j], S1, orr);
            zi[j] = fma2_(zi[j], S1, oii);
        }

        // unscramble: lane L, slot t <- z[8L + t] (from lane rev5(L), reg rev3(t))
        float nrA[8], nrB[8], niA[8], niB[8];
        {
            const int rev3t[8] = {0, 4, 2, 6, 1, 5, 3, 7};
            #pragma unroll
            for (int t = 0; t < 8; t++) {
                float2 vr = up2(zr[rev3t[t]]);
                float2 vi = up2(zi[rev3t[t]]);
                nrA[t] = __shfl_sync(0xffffffffu, vr.x, rl);
                nrB[t] = __shfl_sync(0xffffffffu, vr.y, rl);
                niA[t] = __shfl_sync(0xffffffffu, vi.x, rl);
                niB[t] = __shfl_sync(0xffffffffu, vi.y, rl);
            }
        }

        // unwindowed float4 stores, XOR-swizzled (conflict-free, R3 addressing)
        {
            float4* rowA4 = (float4*)(fr + lfA * 512);
            float4* rowB4 = (float4*)(fr + lfB * 512);
            #pragma unroll
            for (int q = 0; q < 4; q++) {
                int i4 = 4 * lane + q;
                int p4 = SWZ4(i4);
                if (vA) rowA4[p4] = make_float4(nrA[2 * q], niA[2 * q], nrA[2 * q + 1], niA[2 * q + 1]);
                if (vB) rowB4[p4] = make_float4(nrB[2 * q], niB[2 * q], nrB[2 * q + 1], niB[2 * q + 1]);
            }
        }
    }
    __syncthreads();

    // ---- gather overlap-add with window applied here (packed fma) ----
    const int owned = (group == NGROUPS - 1) ? (G * HOP + 384) : (G * HOP);
    const int n4 = owned >> 2;
    const int sbase = f0 * HOP;
    float* outb = out + (size_t)batch * OUT_LEN;
    for (int t = tid; t < n4; t += 256) {
        int s0 = 4 * t;
        int qf = s0 >> 7;
        int r4 = (s0 & 127) >> 2;
        u64 a0 = 0ULL, a1 = 0ULL;
        #pragma unroll
        for (int d = 0; d < 4; d++) {
            int lf = qf - d + 3;
            if (lf < FRAMES_SH) {
                int i4 = r4 + (d << 5);
                int p4 = SWZ4(i4);
                float4 v = *(const float4*)&fr[lf * 512 + 4 * p4];
                float4 w = *(const float4*)&ww[4 * i4];
                a0 = fma2_(pk2(v.x, v.y), pk2(w.x, w.y), a0);
                a1 = fma2_(pk2(v.z, v.w), pk2(w.z, w.w), a1);
            }
        }
        int S = sbase + s0;
        float2 o0 = up2(a0), o1 = up2(a1);
        if (S + 3 < OUT_LEN) {
            outb[S] = o0.x; outb[S + 1] = o0.y; outb[S + 2] = o1.x; outb[S + 3] = o1.y;
        } else {
            if (S     < OUT_LEN) outb[S]     = o0.x;
            if (S + 1 < OUT_LEN) outb[S + 1] = o0.y;
            if (S + 2 < OUT_LEN) outb[S + 2] = o1.x;
        }
    }
}

extern "C" void kernel_launch(void* const* d_in, const int* in_sizes, int n_in,
                              void* d_out, int out_size)
{
    const float* stft_real = (const float*)d_in[0];
    const float* stft_imag = (const float*)d_in[1];
    float* out = (float*)d_out;
    (void)in_sizes; (void)n_in; (void)out_size;

    cudaFuncSetAttribute(istft_kernel,
                         cudaFuncAttributeMaxDynamicSharedMemorySize, SMEM_BYTES);
    dim3 grid(NGROUPS, BATCH);
    istft_kernel<<<grid, 256, SMEM_BYTES>>>(stft_real, stft_imag, out);
}

// round 6
// speedup vs baseline: 1.4510x; 1.4510x over previous
#include <cuda_runtime.h>
#include <math_constants.h>

#define BATCH     16
#define FRAMES    4000
#define BINS      257
#define HOP       128
#define G         25
#define NGROUPS   160
#define FRAMES_SH 28
#define OUT_LEN   512383
#define SWZ4(i)   ((i) ^ (((i) >> 3) & 7))
#define SWZ2(m)   ((m) ^ ((((m) >> 4) & 7) << 1))

// dynamic smem layout (bytes)
#define OFF_FR    0                 // 28*512*4 = 57344
#define OFF_WIN   57344             // 256 float2 (swizzled, windowed pairs) = 2048
#define OFF_PRT   59392             // 256 float2 prerot (cos, sin) = 2048
#define SMEM_BYTES 61440

__global__ __launch_bounds__(256, 3)
void istft_kernel(const float* __restrict__ xr,
                  const float* __restrict__ xi,
                  float* __restrict__ out)
{
    extern __shared__ __align__(16) char smem_raw[];
    float*  fr   = (float*)(smem_raw + OFF_FR);
    float2* ww2s = (float2*)(smem_raw + OFF_WIN);
    float2* prt  = (float2*)(smem_raw + OFF_PRT);

    const int tid   = threadIdx.x;     // 256
    const int warp  = tid >> 5;
    const int lane  = tid & 31;
    const int group = blockIdx.x;
    const int batch = blockIdx.y;
    const int f0     = group * G;
    const int fstart = f0 - 3;

    // windowed pair table, swizzled: slot SWZ2(m) = (w[2m], w[2m+1]) / 768
    {
        int m = tid;                       // 0..255
        float w0 = (0.5f - 0.5f * cosf(2.0f * CUDART_PI_F * (float)(2 * m)     * (1.0f / 512.0f))) * (1.0f / 768.0f);
        float w1 = (0.5f - 0.5f * cosf(2.0f * CUDART_PI_F * (float)(2 * m + 1) * (1.0f / 512.0f))) * (1.0f / 768.0f);
        ww2s[SWZ2(m)] = make_float2(w0, w1);
        // prerot: e^{i*pi*k/256}
        float s, c;
        sincosf(CUDART_PI_F * (float)m * (1.0f / 256.0f), &s, &c);
        prt[m] = make_float2(c, s);
    }
    if (group == 0)
        for (int i = tid; i < 3 * 512; i += 256) fr[i] = 0.f;
    __syncthreads();

    // ---- per-lane twiddles (frame-invariant) ----
    float s128, c128; __sincosf(CUDART_PI_F * (float)lane * (1.0f / 128.0f), &s128, &c128);
    float s64,  c64;  __sincosf(CUDART_PI_F * (float)lane * (1.0f / 64.0f),  &s64,  &c64);
    float s32,  c32;  __sincosf(CUDART_PI_F * (float)lane * (1.0f / 32.0f),  &s32,  &c32);
    float s16,  c16;  __sincosf(CUDART_PI_F * (float)(lane & 15) * (1.0f / 16.0f), &s16, &c16);
    float s8t,  c8t;  __sincosf(CUDART_PI_F * (float)(lane & 7)  * (1.0f / 8.0f),  &s8t, &c8t);
    float s4t,  c4t;  __sincosf(CUDART_PI_F * (float)(lane & 3)  * (1.0f / 4.0f),  &s4t, &c4t);

    const float R2 = 0.70710678118654752f;
    float w128c[4], w128s[4];
    w128c[0] = c128;               w128s[0] = s128;
    w128c[1] = R2 * (c128 - s128); w128s[1] = R2 * (c128 + s128);
    w128c[2] = -s128;              w128s[2] = c128;
    w128c[3] = -R2 * (c128 + s128); w128s[3] = R2 * (c128 - s128);

    const int rl = (int)(__brev((unsigned)lane) >> 27);     // rev5(lane)
    const int mBase = rl * 8;
    const int vx = ((rl >> 1) & 7) << 1;                    // SWZ2 xor term for this lane
    const size_t bbase = (size_t)batch * FRAMES;

    // per-lane stage constants (s, Wc, Ws), branch-free butterflies
    const float sg16 = (lane & 16) ? -1.f : 1.f;
    const float W16c = (lane & 16) ? c16 : 1.f, W16s = (lane & 16) ? s16 : 0.f;
    const float sg8  = (lane & 8)  ? -1.f : 1.f;
    const float W8c  = (lane & 8)  ? c8t : 1.f, W8s  = (lane & 8)  ? s8t : 0.f;
    const float sg4  = (lane & 4)  ? -1.f : 1.f;
    const float W4c  = (lane & 4)  ? c4t : 1.f, W4s  = (lane & 4)  ? s4t : 0.f;
    const float sg2  = (lane & 2)  ? -1.f : 1.f;
    const bool  rot2 = (lane & 2) && (lane & 1);
    const float W2c  = rot2 ? 0.f : 1.f, W2s = rot2 ? 1.f : 0.f;
    const float sg1  = (lane & 1)  ? -1.f : 1.f;

    for (int lf = warp; lf < FRAMES_SH; lf += 8) {
        if (group == 0 && lf < 3) continue;
        const int f = fstart + lf;

        const float* pre = xr + (bbase + f) * BINS;
        const float* pim = xi + (bbase + f) * BINS;

        float zr[8], zi[8];

        // Hermitian pack + pre-rotation, k = 32*j + lane (coalesced)
        #pragma unroll
        for (int j = 0; j < 8; j++) {
            int k  = 32 * j + lane;
            int km = 256 - k;
            float ar = pre[k];
            float br = pre[km];
            float ai, mi;
            if (k == 0) { ai = 0.f; mi = 0.f; }
            else        { ai = pim[k]; mi = pim[km]; }
            float er = ar + br, ei = ai - mi;    // bi = -mi
            float dr = ar - br, di = ai + mi;
            float2 t = prt[k];                   // (cos, sin) pi*k/256
            zr[j] = fmaf(-di, t.x, fmaf(-dr, t.y, er));
            zi[j] = fmaf(-di, t.y, fmaf( dr, t.x, ei));
        }

        // ---- register stages (h = 128, 64, 32) ----
        #pragma unroll
        for (int j = 0; j < 4; j++) {
            float tr = zr[j] - zr[j + 4], ti = zi[j] - zi[j + 4];
            zr[j] += zr[j + 4]; zi[j] += zi[j + 4];
            zr[j + 4] = tr * w128c[j] - ti * w128s[j];
            zi[j + 4] = tr * w128s[j] + ti * w128c[j];
        }
        #define RB(A,B,CC,SS) { float tr=zr[A]-zr[B], ti=zi[A]-zi[B]; \
            zr[A]+=zr[B]; zi[A]+=zi[B]; zr[B]=tr*(CC)-ti*(SS); zi[B]=tr*(SS)+ti*(CC); }
        RB(0, 2, c64, s64)  RB(4, 6, c64, s64)
        RB(1, 3, -s64, c64) RB(5, 7, -s64, c64)
        RB(0, 1, c32, s32) RB(2, 3, c32, s32)
        RB(4, 5, c32, s32) RB(6, 7, c32, s32)
        #undef RB

        // ---- lane stages (branch-free): m = 16, 8, 4, 2 ----
        #define LSTAGE(MASK, SG, WC, WS)                                        \
        {                                                                       \
            _Pragma("unroll")                                                   \
            for (int j = 0; j < 8; j++) {                                       \
                float orr = __shfl_xor_sync(0xffffffffu, zr[j], (MASK));        \
                float oii = __shfl_xor_sync(0xffffffffu, zi[j], (MASK));        \
                float tr = fmaf(zr[j], (SG), orr);                              \
                float ti = fmaf(zi[j], (SG), oii);                              \
                zr[j] = tr * (WC) - ti * (WS);                                  \
                zi[j] = tr * (WS) + ti * (WC);                                  \
            }                                                                   \
        }
        LSTAGE(16, sg16, W16c, W16s)
        LSTAGE(8,  sg8,  W8c,  W8s)
        LSTAGE(4,  sg4,  W4c,  W4s)
        LSTAGE(2,  sg2,  W2c,  W2s)
        #undef LSTAGE
        // m = 1 (W = 1)
        #pragma unroll
        for (int j = 0; j < 8; j++) {
            float orr = __shfl_xor_sync(0xffffffffu, zr[j], 1);
            float oii = __shfl_xor_sync(0xffffffffu, zi[j], 1);
            zr[j] = fmaf(zr[j], sg1, orr);
            zi[j] = fmaf(zi[j], sg1, oii);
        }

        // ---- direct bit-reversed windowed stores ----
        // position (lane, j) holds z[m], m = 8*rev5(lane) + rev3(j)
        {
            float2* row2 = (float2*)(fr + lf * 512);
            const int rev3[8] = {0, 4, 2, 6, 1, 5, 3, 7};
            #pragma unroll
            for (int j = 0; j < 8; j++) {
                int p2 = (mBase + rev3[j]) ^ vx;          // SWZ2(m)
                float2 w2 = ww2s[p2];
                row2[p2] = make_float2(zr[j] * w2.x, zi[j] * w2.y);
            }
        }
    }
    __syncthreads();

    // ---- gather overlap-add (window already applied; pure adds) ----
    const int owned = (group == NGROUPS - 1) ? (G * HOP + 384) : (G * HOP);
    const int n4 = owned >> 2;
    const int sbase = f0 * HOP;
    float* outb = out + (size_t)batch * OUT_LEN;
    for (int t = tid; t < n4; t += 256) {
        int s0 = 4 * t;
        int qf = s0 >> 7;
        int r4 = (s0 & 127) >> 2;
        float a0 = 0.f, a1 = 0.f, a2 = 0.f, a3 = 0.f;
        #pragma unroll
        for (int d = 0; d < 4; d++) {
            int lf = qf - d + 3;
            if (lf < FRAMES_SH) {
                int i4 = r4 + (d << 5);
                int p4 = SWZ4(i4);
                float4 v = *(const float4*)&fr[lf * 512 + 4 * p4];
                a0 += v.x; a1 += v.y; a2 += v.z; a3 += v.w;
            }
        }
        int S = sbase + s0;
        if (S + 3 < OUT_LEN) {
            outb[S] = a0; outb[S + 1] = a1; outb[S + 2] = a2; outb[S + 3] = a3;
        } else {
            if (S     < OUT_LEN) outb[S]     = a0;
            if (S + 1 < OUT_LEN) outb[S + 1] = a1;
            if (S + 2 < OUT_LEN) outb[S + 2] = a2;
        }
    }
}

extern "C" void kernel_launch(void* const* d_in, const int* in_sizes, int n_in,
                              void* d_out, int out_size)
{
    const float* stft_real = (const float*)d_in[0];
    const float* stft_imag = (const float*)d_in[1];
    float* out = (float*)d_out;
    (void)in_sizes; (void)n_in; (void)out_size;

    cudaFuncSetAttribute(istft_kernel,
                         cudaFuncAttributeMaxDynamicSharedMemorySize, SMEM_BYTES);
    dim3 grid(NGROUPS, BATCH);
    istft_kernel<<<grid, 256, SMEM_BYTES>>>(stft_real, stft_imag, out);
}